// round 5
// baseline (speedup 1.0000x reference)
#include <cuda_runtime.h>
#include <cstdint>

// MeanAggregator: out[i] = sum_{j in edges[i]} nodes[edges[i][j]] / n_nodes
// Shapes: N = 40000, DEG = 16, D = 128 (fp32); edges buffer is int32
// (JAX silently downgrades int64 without x64 mode).
//
// R5: 2 nodes per warp -> 32 outstanding LDG.128 gathers per warp (was 16),
// int4-vectorized index loads (4 LDG instead of 16 per node). Attacks the
// latency-bound profile seen in R4 (L1=60%, L2=61%, issue=31%, nothing capped).

#define D_FEAT 128
#define D_VEC (D_FEAT / 4)   // 32 float4 per row = 1 per lane
#define DEG_FAST 16

__global__ __launch_bounds__(256) void mean_agg2_kernel(
    const float4* __restrict__ nodes,   // [n_nodes * 32] float4
    const int* __restrict__ edges,      // [n_nodes * deg] int32
    float4* __restrict__ out,           // [n_nodes * 32] float4
    int n_nodes, int deg, float inv_n)
{
    const int warp_id = (blockIdx.x * blockDim.x + threadIdx.x) >> 5;
    const int lane = threadIdx.x & 31;

    const int nodeA = warp_id * 2;
    const int nodeB = nodeA + 1;
    if (nodeA >= n_nodes) return;
    const bool hasB = (nodeB < n_nodes);

    float4 accA = make_float4(0.f, 0.f, 0.f, 0.f);
    float4 accB = make_float4(0.f, 0.f, 0.f, 0.f);

    if (deg == DEG_FAST) {
        // Vectorized index loads: 4 int4 per node instead of 16 scalar LDGs.
        const int4* eA = (const int4*)(edges + (long long)nodeA * DEG_FAST);
        // If no B node, alias B's indices to A's (valid memory, result discarded).
        const int4* eB = hasB ? (const int4*)(edges + (long long)nodeB * DEG_FAST) : eA;

        int idxA[DEG_FAST], idxB[DEG_FAST];
#pragma unroll
        for (int q = 0; q < 4; ++q) {
            int4 a = __ldg(&eA[q]);
            int4 b = __ldg(&eB[q]);
            idxA[q * 4 + 0] = a.x; idxA[q * 4 + 1] = a.y;
            idxA[q * 4 + 2] = a.z; idxA[q * 4 + 3] = a.w;
            idxB[q * 4 + 0] = b.x; idxB[q * 4 + 1] = b.y;
            idxB[q * 4 + 2] = b.z; idxB[q * 4 + 3] = b.w;
        }

        // 32 independent gathers in flight (2 interleaved streams of 16).
#pragma unroll
        for (int j = 0; j < DEG_FAST; ++j) {
            float4 va = __ldg(&nodes[idxA[j] * D_VEC + lane]);
            float4 vb = __ldg(&nodes[idxB[j] * D_VEC + lane]);
            accA.x += va.x; accA.y += va.y; accA.z += va.z; accA.w += va.w;
            accB.x += vb.x; accB.y += vb.y; accB.z += vb.z; accB.w += vb.w;
        }
    } else {
        // Generic path: process the (up to) two nodes with unroll-4 MLP.
        for (int p = 0; p < 2; ++p) {
            int node = nodeA + p;
            if (node >= n_nodes) break;
            const int* e = edges + (long long)node * deg;
            float4 acc = make_float4(0.f, 0.f, 0.f, 0.f);
            int j = 0;
            for (; j + 4 <= deg; j += 4) {
                int i0 = __ldg(&e[j + 0]);
                int i1 = __ldg(&e[j + 1]);
                int i2 = __ldg(&e[j + 2]);
                int i3 = __ldg(&e[j + 3]);
                float4 v0 = __ldg(&nodes[i0 * D_VEC + lane]);
                float4 v1 = __ldg(&nodes[i1 * D_VEC + lane]);
                float4 v2 = __ldg(&nodes[i2 * D_VEC + lane]);
                float4 v3 = __ldg(&nodes[i3 * D_VEC + lane]);
                acc.x += v0.x + v1.x + v2.x + v3.x;
                acc.y += v0.y + v1.y + v2.y + v3.y;
                acc.z += v0.z + v1.z + v2.z + v3.z;
                acc.w += v0.w + v1.w + v2.w + v3.w;
            }
            for (; j < deg; ++j) {
                int i0 = __ldg(&e[j]);
                float4 v = __ldg(&nodes[i0 * D_VEC + lane]);
                acc.x += v.x; acc.y += v.y; acc.z += v.z; acc.w += v.w;
            }
            if (p == 0) accA = acc; else accB = acc;
        }
    }

    out[(long long)nodeA * D_VEC + lane] =
        make_float4(accA.x * inv_n, accA.y * inv_n, accA.z * inv_n, accA.w * inv_n);
    if (hasB) {
        out[(long long)nodeB * D_VEC + lane] =
            make_float4(accB.x * inv_n, accB.y * inv_n, accB.z * inv_n, accB.w * inv_n);
    }
}

extern "C" void kernel_launch(void* const* d_in, const int* in_sizes, int n_in,
                              void* d_out, int out_size)
{
    const float4* nodes = (const float4*)d_in[0];
    const int* edges = (const int*)d_in[1];
    float4* out = (float4*)d_out;

    const int n_nodes = in_sizes[0] / D_FEAT;
    const int deg = in_sizes[1] / n_nodes;
    const float inv_n = 1.0f / (float)n_nodes;

    // 2 nodes per warp, 8 warps (256 threads) per block -> 16 nodes per block.
    const int threads = 256;
    const int nodes_per_block = (threads / 32) * 2;
    const int blocks = (n_nodes + nodes_per_block - 1) / nodes_per_block;  // 2500
    mean_agg2_kernel<<<blocks, threads>>>(nodes, edges, out, n_nodes, deg, inv_n);
}

// round 6
// speedup vs baseline: 1.1819x; 1.1819x over previous
#include <cuda_runtime.h>
#include <cstdint>

// MeanAggregator: out[i] = sum_{j in edges[i]} nodes[edges[i][j]] / n_nodes
// Shapes: N = 40000, DEG = 16, D = 128 (fp32); edges buffer is int32.
//
// R6: back to 1 node/warp (R4 grid), but force real MLP: gathers issued in
// explicit batches of 8 distinct float4 destinations BEFORE any accumulate,
// so ptxas must keep 32 payload registers in flight (R4/R5 collapsed to
// regs=32 and serialized the load->add chains; MLP_eff ~4).

#define D_FEAT 128
#define D_VEC (D_FEAT / 4)   // 32 float4 per row = 1 per lane
#define DEG_FAST 16

__global__ __launch_bounds__(256) void mean_agg3_kernel(
    const float4* __restrict__ nodes,   // [n_nodes * 32] float4
    const int* __restrict__ edges,      // [n_nodes * deg] int32
    float4* __restrict__ out,           // [n_nodes * 32] float4
    int n_nodes, int deg, float inv_n)
{
    const int warp_id = (blockIdx.x * blockDim.x + threadIdx.x) >> 5;
    const int lane = threadIdx.x & 31;
    if (warp_id >= n_nodes) return;

    float4 acc = make_float4(0.f, 0.f, 0.f, 0.f);

    if (deg == DEG_FAST) {
        // Vectorized index load: 4 x int4 (uniform across warp -> broadcast).
        const int4* e4 = (const int4*)(edges + (long long)warp_id * DEG_FAST);
        int idx[DEG_FAST];
#pragma unroll
        for (int q = 0; q < 4; ++q) {
            int4 a = __ldg(&e4[q]);
            idx[q * 4 + 0] = a.x; idx[q * 4 + 1] = a.y;
            idx[q * 4 + 2] = a.z; idx[q * 4 + 3] = a.w;
        }

        // Two batches of 8: all 8 loads issued into distinct registers before
        // any consumer -> scoreboard window of 8 outstanding LDG.E.128.
        float4 v0, v1, v2, v3, v4, v5, v6, v7;

        v0 = __ldg(&nodes[idx[0] * D_VEC + lane]);
        v1 = __ldg(&nodes[idx[1] * D_VEC + lane]);
        v2 = __ldg(&nodes[idx[2] * D_VEC + lane]);
        v3 = __ldg(&nodes[idx[3] * D_VEC + lane]);
        v4 = __ldg(&nodes[idx[4] * D_VEC + lane]);
        v5 = __ldg(&nodes[idx[5] * D_VEC + lane]);
        v6 = __ldg(&nodes[idx[6] * D_VEC + lane]);
        v7 = __ldg(&nodes[idx[7] * D_VEC + lane]);

        // Pairwise tree keeps dependency chains short.
        float4 s01, s23, s45, s67;
        s01.x = v0.x + v1.x; s01.y = v0.y + v1.y; s01.z = v0.z + v1.z; s01.w = v0.w + v1.w;
        s23.x = v2.x + v3.x; s23.y = v2.y + v3.y; s23.z = v2.z + v3.z; s23.w = v2.w + v3.w;
        s45.x = v4.x + v5.x; s45.y = v4.y + v5.y; s45.z = v4.z + v5.z; s45.w = v4.w + v5.w;
        s67.x = v6.x + v7.x; s67.y = v6.y + v7.y; s67.z = v6.z + v7.z; s67.w = v6.w + v7.w;
        acc.x = (s01.x + s23.x) + (s45.x + s67.x);
        acc.y = (s01.y + s23.y) + (s45.y + s67.y);
        acc.z = (s01.z + s23.z) + (s45.z + s67.z);
        acc.w = (s01.w + s23.w) + (s45.w + s67.w);

        v0 = __ldg(&nodes[idx[8]  * D_VEC + lane]);
        v1 = __ldg(&nodes[idx[9]  * D_VEC + lane]);
        v2 = __ldg(&nodes[idx[10] * D_VEC + lane]);
        v3 = __ldg(&nodes[idx[11] * D_VEC + lane]);
        v4 = __ldg(&nodes[idx[12] * D_VEC + lane]);
        v5 = __ldg(&nodes[idx[13] * D_VEC + lane]);
        v6 = __ldg(&nodes[idx[14] * D_VEC + lane]);
        v7 = __ldg(&nodes[idx[15] * D_VEC + lane]);

        s01.x = v0.x + v1.x; s01.y = v0.y + v1.y; s01.z = v0.z + v1.z; s01.w = v0.w + v1.w;
        s23.x = v2.x + v3.x; s23.y = v2.y + v3.y; s23.z = v2.z + v3.z; s23.w = v2.w + v3.w;
        s45.x = v4.x + v5.x; s45.y = v4.y + v5.y; s45.z = v4.z + v5.z; s45.w = v4.w + v5.w;
        s67.x = v6.x + v7.x; s67.y = v6.y + v7.y; s67.z = v6.z + v7.z; s67.w = v6.w + v7.w;
        acc.x += (s01.x + s23.x) + (s45.x + s67.x);
        acc.y += (s01.y + s23.y) + (s45.y + s67.y);
        acc.z += (s01.z + s23.z) + (s45.z + s67.z);
        acc.w += (s01.w + s23.w) + (s45.w + s67.w);
    } else {
        // Generic path: unroll by 4.
        const int* e = edges + (long long)warp_id * deg;
        int j = 0;
        for (; j + 4 <= deg; j += 4) {
            int i0 = __ldg(&e[j + 0]);
            int i1 = __ldg(&e[j + 1]);
            int i2 = __ldg(&e[j + 2]);
            int i3 = __ldg(&e[j + 3]);
            float4 v0 = __ldg(&nodes[i0 * D_VEC + lane]);
            float4 v1 = __ldg(&nodes[i1 * D_VEC + lane]);
            float4 v2 = __ldg(&nodes[i2 * D_VEC + lane]);
            float4 v3 = __ldg(&nodes[i3 * D_VEC + lane]);
            acc.x += (v0.x + v1.x) + (v2.x + v3.x);
            acc.y += (v0.y + v1.y) + (v2.y + v3.y);
            acc.z += (v0.z + v1.z) + (v2.z + v3.z);
            acc.w += (v0.w + v1.w) + (v2.w + v3.w);
        }
        for (; j < deg; ++j) {
            int i0 = __ldg(&e[j]);
            float4 v = __ldg(&nodes[i0 * D_VEC + lane]);
            acc.x += v.x; acc.y += v.y; acc.z += v.z; acc.w += v.w;
        }
    }

    out[(long long)warp_id * D_VEC + lane] =
        make_float4(acc.x * inv_n, acc.y * inv_n, acc.z * inv_n, acc.w * inv_n);
}

extern "C" void kernel_launch(void* const* d_in, const int* in_sizes, int n_in,
                              void* d_out, int out_size)
{
    const float4* nodes = (const float4*)d_in[0];
    const int* edges = (const int*)d_in[1];
    float4* out = (float4*)d_out;

    const int n_nodes = in_sizes[0] / D_FEAT;
    const int deg = in_sizes[1] / n_nodes;
    const float inv_n = 1.0f / (float)n_nodes;

    // One warp per node, 8 warps (256 threads) per block.
    const int threads = 256;
    const int warps_per_block = threads / 32;
    const int blocks = (n_nodes + warps_per_block - 1) / warps_per_block;  // 5000
    mean_agg3_kernel<<<blocks, threads>>>(nodes, edges, out, n_nodes, deg, inv_n);
}

// round 7
// speedup vs baseline: 1.2071x; 1.0213x over previous
#include <cuda_runtime.h>
#include <cstdint>

// MeanAggregator: out[i] = sum_{j in edges[i]} nodes[edges[i][j]] / n_nodes
// Shapes: N = 40000, DEG = 16, D = 128 (fp32); edges buffer is int32.
//
// R7: ptxas defeated C-level load batching three times (regs pinned at 32,
// MLP_eff ~4). Force true MLP=16 with asm volatile ld.global.nc.v4.f32:
// volatile asm preserves issue order and keeps all 64 payload registers
// live until the reduction, so ptxas cannot serialize the gathers.

#define D_FEAT 128
#define D_VEC (D_FEAT / 4)   // 32 float4 per row = 1 per lane
#define DEG_FAST 16

#define LDG128NC(dst, ptr)                                                   \
    asm volatile("ld.global.nc.v4.f32 {%0,%1,%2,%3}, [%4];"                  \
                 : "=f"(dst.x), "=f"(dst.y), "=f"(dst.z), "=f"(dst.w)        \
                 : "l"(ptr))

__global__ __launch_bounds__(256) void mean_agg4_kernel(
    const float4* __restrict__ nodes,   // [n_nodes * 32] float4
    const int* __restrict__ edges,      // [n_nodes * deg] int32
    float4* __restrict__ out,           // [n_nodes * 32] float4
    int n_nodes, int deg, float inv_n)
{
    const int warp_id = (blockIdx.x * blockDim.x + threadIdx.x) >> 5;
    const int lane = threadIdx.x & 31;
    if (warp_id >= n_nodes) return;

    float4 acc = make_float4(0.f, 0.f, 0.f, 0.f);

    if (deg == DEG_FAST) {
        // Vectorized index load: 4 x int4 (uniform across warp -> broadcast).
        const int4* e4 = (const int4*)(edges + (long long)warp_id * DEG_FAST);
        int idx[DEG_FAST];
#pragma unroll
        for (int q = 0; q < 4; ++q) {
            int4 a = __ldg(&e4[q]);
            idx[q * 4 + 0] = a.x; idx[q * 4 + 1] = a.y;
            idx[q * 4 + 2] = a.z; idx[q * 4 + 3] = a.w;
        }

        // Issue ALL 16 gathers back-to-back (volatile asm = fixed issue
        // order, 64 live payload regs -> ptxas cannot collapse the window).
        float4 v[DEG_FAST];
#pragma unroll
        for (int j = 0; j < DEG_FAST; ++j) {
            const float4* p = nodes + (size_t)((unsigned)idx[j] * D_VEC + lane);
            LDG128NC(v[j], p);
        }

        // Tree reduction (short dependency chains).
        float4 s[8];
#pragma unroll
        for (int j = 0; j < 8; ++j) {
            s[j].x = v[2 * j].x + v[2 * j + 1].x;
            s[j].y = v[2 * j].y + v[2 * j + 1].y;
            s[j].z = v[2 * j].z + v[2 * j + 1].z;
            s[j].w = v[2 * j].w + v[2 * j + 1].w;
        }
#pragma unroll
        for (int j = 0; j < 4; ++j) {
            s[j].x = s[2 * j].x + s[2 * j + 1].x;
            s[j].y = s[2 * j].y + s[2 * j + 1].y;
            s[j].z = s[2 * j].z + s[2 * j + 1].z;
            s[j].w = s[2 * j].w + s[2 * j + 1].w;
        }
        acc.x = (s[0].x + s[1].x) + (s[2].x + s[3].x);
        acc.y = (s[0].y + s[1].y) + (s[2].y + s[3].y);
        acc.z = (s[0].z + s[1].z) + (s[2].z + s[3].z);
        acc.w = (s[0].w + s[1].w) + (s[2].w + s[3].w);
    } else {
        // Generic path: unroll by 4.
        const int* e = edges + (long long)warp_id * deg;
        int j = 0;
        for (; j + 4 <= deg; j += 4) {
            int i0 = __ldg(&e[j + 0]);
            int i1 = __ldg(&e[j + 1]);
            int i2 = __ldg(&e[j + 2]);
            int i3 = __ldg(&e[j + 3]);
            float4 v0 = __ldg(&nodes[i0 * D_VEC + lane]);
            float4 v1 = __ldg(&nodes[i1 * D_VEC + lane]);
            float4 v2 = __ldg(&nodes[i2 * D_VEC + lane]);
            float4 v3 = __ldg(&nodes[i3 * D_VEC + lane]);
            acc.x += (v0.x + v1.x) + (v2.x + v3.x);
            acc.y += (v0.y + v1.y) + (v2.y + v3.y);
            acc.z += (v0.z + v1.z) + (v2.z + v3.z);
            acc.w += (v0.w + v1.w) + (v2.w + v3.w);
        }
        for (; j < deg; ++j) {
            int i0 = __ldg(&e[j]);
            float4 v = __ldg(&nodes[i0 * D_VEC + lane]);
            acc.x += v.x; acc.y += v.y; acc.z += v.z; acc.w += v.w;
        }
    }

    out[(long long)warp_id * D_VEC + lane] =
        make_float4(acc.x * inv_n, acc.y * inv_n, acc.z * inv_n, acc.w * inv_n);
}

extern "C" void kernel_launch(void* const* d_in, const int* in_sizes, int n_in,
                              void* d_out, int out_size)
{
    const float4* nodes = (const float4*)d_in[0];
    const int* edges = (const int*)d_in[1];
    float4* out = (float4*)d_out;

    const int n_nodes = in_sizes[0] / D_FEAT;
    const int deg = in_sizes[1] / n_nodes;
    const float inv_n = 1.0f / (float)n_nodes;

    // One warp per node, 8 warps (256 threads) per block.
    const int threads = 256;
    const int warps_per_block = threads / 32;
    const int blocks = (n_nodes + warps_per_block - 1) / warps_per_block;  // 5000
    mean_agg4_kernel<<<blocks, threads>>>(nodes, edges, out, n_nodes, deg, inv_n);
}